// round 12
// baseline (speedup 1.0000x reference)
#include <cuda_runtime.h>
#include <math.h>

#define NH 25
#define NS 20
#define DT (1.0f/60.0f)
#define EPS_ 1e-4f
#define PQ 5.0f
#define QV_ 200.0f
#define QA_ 1.0f

#define WARPS 8
#define THREADS 256
#define RPW 16                 // rows per warp (2 threads/row)
#define RPB (WARPS * RPW)      // 128 rows per block
#define NCOEF 68               // q[25] | beta[20] | gamma[20] | pad[3]

__device__ float d_coef[NCOEF];
__device__ unsigned d_flags[32 * 32];   // replicated flag, one per 128B line

__device__ __forceinline__ unsigned smem_u32(const void* p) {
    return (unsigned)__cvta_generic_to_shared(p);
}
__device__ __forceinline__ unsigned ld_acquire(const unsigned* p) {
    unsigned v;
    asm volatile("ld.global.acquire.gpu.b32 %0, [%1];" : "=r"(v) : "l"(p));
    return v;
}
__device__ __forceinline__ void st_release(unsigned* p, unsigned v) {
    asm volatile("st.global.release.gpu.b32 [%0], %1;" :: "l"(p), "r"(v));
}

// ---------------------------------------------------------------------------
// Coefficient solve (block 0, warp 0). Verified closed-form math (rel_err
// 6.6e-7 since R4); Gauss-Jordan matrix in SMEM scratch so the kernel-wide
// register cap causes no spills. All shuffles warp-uniform.
// ---------------------------------------------------------------------------
__device__ void solve_coeffs(const float* __restrict__ Af,
                             const float* __restrict__ Lq,
                             int lane, float* __restrict__ Rs /* >= 20*21 floats */) {
    const unsigned FULL = 0xffffffffu;
    const int lnh = (lane < NH) ? lane : 0;
    const float af = (lane < NH) ? Af[lane] : 0.0f;

    float tk = 0.0f;
    #pragma unroll 5
    for (int j = 0; j < NH; j++)
        tk = fmaf(Lq[j * NH + lnh], __shfl_sync(FULL, af, j), tk);

    float q = EPS_ * af;
    #pragma unroll 5
    for (int k = 0; k < NH; k++)
        q = fmaf(Lq[lnh * NH + k], __shfl_sync(FULL, tk, k), q);
    if (lane < NH) d_coef[lane] = q;

    float av = (lane < NH) ? q * af : 0.0f;
    #pragma unroll
    for (int o = 16; o; o >>= 1) av += __shfl_xor_sync(FULL, av, o);
    const float alpha = av;

    float M0 = 0.f, M1 = 0.f, M2 = 0.f;
    for (int r = lane; r < NS; r++) {
        float w = (r == NS - 1) ? PQ : 1.0f;
        float d = (float)(r - lane);
        M0 += w;
        M1 = fmaf(w, d, M1);
        M2 = fmaf(w, d * d, M2);
    }

    for (int c2 = 0; c2 < NS; c2++) {
        int m = lane > c2 ? lane : c2;
        if (m >= NS) m = NS - 1;
        float m0 = __shfl_sync(FULL, M0, m);
        float m1 = __shfl_sync(FULL, M1, m);
        float m2 = __shfl_sync(FULL, M2, m);
        float dd = fabsf((float)(lane - c2));
        float v = 2.0f * DT * DT * fmaf(alpha, fmaf(dd, m1, m2), QV_ * m0);
        if (lane == c2) v += 2.0f * QA_ + EPS_;
        if (lane < NS) Rs[lane * 21 + c2] = v;
    }
    float b1 = M1;
    float b2 = fmaf(alpha, fmaf((float)(lane + 1), M1, M2), QV_ * M0);
    __syncwarp();

    float myinv = 1.0f;
    for (int k = 0; k < NS; k++) {
        float pivk = Rs[k * 21 + k];
        float inv = __frcp_rn(pivk);
        float f = (lane < NS) ? Rs[lane * 21 + k] * inv : 0.0f;
        if (lane == k) { myinv = inv; f = 0.0f; }
        if (lane < NS && lane != k) {
            for (int j = k + 1; j < NS; j++)
                Rs[lane * 21 + j] = fmaf(-f, Rs[k * 21 + j], Rs[lane * 21 + j]);
        }
        float p1 = __shfl_sync(FULL, b1, k);
        float p2 = __shfl_sync(FULL, b2, k);
        b1 = fmaf(-f, p1, b1);
        b2 = fmaf(-f, p2, b2);
        __syncwarp();
    }
    float h1 = b1 * myinv;
    float h2 = b2 * myinv;

    float ab = 0.f, ag = 0.f;
    for (int c = 0; c < NS; c++) {
        float hc = __shfl_sync(FULL, h1, c);
        float gc = __shfl_sync(FULL, h2, c);
        if (c <= lane) {
            float w = (float)(lane - c) + 0.5f;
            ab = fmaf(w, hc, ab);
            ag = fmaf(w, gc, ag);
        }
    }
    if (lane < NS) {
        const float f = 2.0f * DT * DT * DT;
        d_coef[NH + lane]      = -f * ab;                              // beta  [25,45)
        d_coef[NH + NS + lane] = fmaf((float)(lane + 1), DT, -f * ag); // gamma [45,65)
    }
    if (lane >= 29) d_coef[65 + (lane - 29)] = 0.0f;   // pad [65,68) only
}

// ---------------------------------------------------------------------------
// Fused kernel, 2 threads per row: half0 dots x[0:12], half1 dots x[12:25];
// combined via shfl_xor. 128 rows/block, launch_bounds(256,7). Output staging
// uses each warp's OWN input region (no cross-warp aliasing — R11 bug fix).
// ---------------------------------------------------------------------------
__global__ void __launch_bounds__(THREADS, 7) mpc_fused(
    const float* __restrict__ x, const float* __restrict__ gp,
    const float* __restrict__ gv, const float* __restrict__ Af,
    const float* __restrict__ Lq, float* __restrict__ out, int nB)
{
    __shared__ float sx[RPB * NH];    // 12.8 KB; block 0: GJ scratch; reused per-warp for out
    __shared__ float scoef[NCOEF];

    const int t = threadIdx.x;
    const int warp = t >> 5;
    const int lane = t & 31;

    if (blockIdx.x == 0) {
        if (warp == 0) {
            solve_coeffs(Af, Lq, lane, sx);
            __threadfence();
            __syncwarp();
            st_release(&d_flags[lane * 32], 1u);   // 32 replicas
        }
        return;
    }

    const int wbase = (blockIdx.x - 1) * RPB + warp * RPW;   // 16 rows per warp
    float* __restrict__ wreg = sx + warp * RPW * NH;         // warp-private 400 floats

    // 1) stage this warp's 16 rows (100 float4) via cp.async
    {
        const float4* __restrict__ xin = (const float4*)(x + (size_t)wbase * NH);
        const long long n4_total = (long long)nB * NH / 4;
        const long long i4base = (long long)wbase * NH / 4;
        #pragma unroll
        for (int i = lane; i < RPW * NH / 4; i += 32) {
            if (i4base + i < n4_total) {
                unsigned d = smem_u32(wreg + 4 * i);
                asm volatile("cp.async.cg.shared.global [%0], [%1], 16;\n"
                             :: "r"(d), "l"(xin + i));
            }
        }
        asm volatile("cp.async.commit_group;\n");
    }

    // 2) prefetch gp/gv (pair-duplicated, coalesced)
    const int row = lane >> 1;
    const int half = lane & 1;
    const int b = wbase + row;
    const bool live = (b < nB);
    const float p = live ? gp[b] : 0.f;
    const float v = live ? gv[b] : 0.f;

    // 3) coefficient readiness (hashed flag line)
    {
        const unsigned* fp = &d_flags[(blockIdx.x & 31) * 32];
        if (ld_acquire(fp) == 0u) {
            while (ld_acquire(fp) == 0u) { __nanosleep(128); }
        }
    }

    // 4) coefficients -> smem (per-warp redundant copy; identical values)
    #pragma unroll
    for (int i = lane; i < NCOEF; i += 32) scoef[i] = d_coef[i];
    __syncwarp();

    // 5) wait staging
    asm volatile("cp.async.wait_group 0;\n");
    __syncwarp();

    const float* __restrict__ sq = scoef;
    const float* __restrict__ sb = scoef + NH;
    const float* __restrict__ sg = scoef + NH + NS;

    // half-dot: half0 -> x[0:12], half1 -> x[12:25]
    const float* __restrict__ xr = wreg + row * NH + half * 12;
    const int qoff = half * 12;
    float part = 0.f;
    #pragma unroll
    for (int j = 0; j < 12; j++) part = fmaf(xr[j], sq[qoff + j], part);
    if (half) part = fmaf(xr[12], sq[24], part);
    const float y = part + __shfl_xor_sync(0xffffffffu, part, 1);

    __syncwarp();   // own-region reads complete before overwrite

    // 6) outputs into the warp's OWN region: row*NS + half*12 (320 <= 400 fits)
    float4* so4 = (float4*)(wreg + row * NS + half * 12);
    const int sbase = half * 12;
    const int n4 = 3 - half;      // half0: 3 float4 (s 0..11), half1: 2 (s 12..19)
    #pragma unroll
    for (int s4 = 0; s4 < 3; s4++) {
        if (s4 < n4) {
            const int s = sbase + 4 * s4;
            float4 r;
            r.x = fmaf(sb[s + 0], y, fmaf(sg[s + 0], v, p));
            r.y = fmaf(sb[s + 1], y, fmaf(sg[s + 1], v, p));
            r.z = fmaf(sb[s + 2], y, fmaf(sg[s + 2], v, p));
            r.w = fmaf(sb[s + 3], y, fmaf(sg[s + 3], v, p));
            so4[s4] = r;
        }
    }
    __syncwarp();

    // 7) coalesced copy out: 16 rows * 20 floats = 80 contiguous float4
    {
        float4* __restrict__ o4 = (float4*)(out + (size_t)wbase * NS);
        const float4* so = (const float4*)wreg;
        const long long o4_total = (long long)nB * NS / 4;
        const long long o4base = (long long)wbase * NS / 4;
        #pragma unroll
        for (int i = lane; i < RPW * NS / 4; i += 32) {
            if (o4base + i < o4_total) o4[i] = so[i];
        }
    }
}

extern "C" void kernel_launch(void* const* d_in, const int* in_sizes, int n_in,
                              void* d_out, int out_size) {
    const float* x  = (const float*)d_in[0];
    const float* gp = (const float*)d_in[1];
    const float* gv = (const float*)d_in[2];
    const float* Af = (const float*)d_in[3];
    const float* Lq = (const float*)d_in[4];
    float* out = (float*)d_out;

    const int nB = in_sizes[0] / NH;
    const int grid = (nB + RPB - 1) / RPB + 1;   // +1: coefficient block
    mpc_fused<<<grid, THREADS>>>(x, gp, gv, Af, Lq, out, nB);
}

// round 14
// speedup vs baseline: 1.2850x; 1.2850x over previous
#include <cuda_runtime.h>
#include <math.h>

#define NH 25
#define NS 20
#define DT (1.0f/60.0f)
#define EPS_ 1e-4f
#define PQ 5.0f
#define QV_ 200.0f
#define QA_ 1.0f

#define WARPS 8
#define ROWS (WARPS * 32)   // 256 rows per row-block
#define NCOEF 68            // q[25] | beta[20] | gamma[20] | pad[3]

__device__ float d_coef[NCOEF];
__device__ unsigned d_flags[32 * 32];   // replicated flag, one per 128B line

__device__ __forceinline__ unsigned smem_u32(const void* p) {
    return (unsigned)__cvta_generic_to_shared(p);
}
__device__ __forceinline__ unsigned ld_acquire(const unsigned* p) {
    unsigned v;
    asm volatile("ld.global.acquire.gpu.b32 %0, [%1];" : "=r"(v) : "l"(p));
    return v;
}
__device__ __forceinline__ void st_release(unsigned* p, unsigned v) {
    asm volatile("st.global.release.gpu.b32 [%0], %1;" :: "l"(p), "r"(v));
}

// ---------------------------------------------------------------------------
// Coefficient solve: one warp, registers + shuffles (verified rel_err 6.6e-7
// since R4). Uncapped registers -> fully register-resident, ~1-2us, runs once
// on block 0 overlapped with the grid's staging.
// ---------------------------------------------------------------------------
__device__ __noinline__ void solve_coeffs(const float* __restrict__ Af,
                                          const float* __restrict__ Lq, int lane) {
    const unsigned FULL = 0xffffffffu;
    const int lnh = (lane < NH) ? lane : 0;
    const float af = (lane < NH) ? Af[lane] : 0.0f;

    float tk = 0.0f;
    #pragma unroll
    for (int j = 0; j < NH; j++)
        tk = fmaf(Lq[j * NH + lnh], __shfl_sync(FULL, af, j), tk);

    float q = EPS_ * af;
    #pragma unroll
    for (int k = 0; k < NH; k++)
        q = fmaf(Lq[lnh * NH + k], __shfl_sync(FULL, tk, k), q);
    if (lane < NH) d_coef[lane] = q;

    float av = (lane < NH) ? q * af : 0.0f;
    #pragma unroll
    for (int o = 16; o; o >>= 1) av += __shfl_xor_sync(FULL, av, o);
    const float alpha = av;

    float M0 = 0.f, M1 = 0.f, M2 = 0.f;
    for (int r = lane; r < NS; r++) {
        float w = (r == NS - 1) ? PQ : 1.0f;
        float d = (float)(r - lane);
        M0 += w;
        M1 = fmaf(w, d, M1);
        M2 = fmaf(w, d * d, M2);
    }

    float R[NS];
    #pragma unroll
    for (int c2 = 0; c2 < NS; c2++) {
        int m = lane > c2 ? lane : c2;
        if (m >= NS) m = NS - 1;
        float m0 = __shfl_sync(FULL, M0, m);
        float m1 = __shfl_sync(FULL, M1, m);
        float m2 = __shfl_sync(FULL, M2, m);
        float dd = fabsf((float)(lane - c2));
        float v = 2.0f * DT * DT * fmaf(alpha, fmaf(dd, m1, m2), QV_ * m0);
        if (lane == c2) v += 2.0f * QA_ + EPS_;
        R[c2] = v;
    }
    float b1 = M1;
    float b2 = fmaf(alpha, fmaf((float)(lane + 1), M1, M2), QV_ * M0);

    float myinv = 1.0f;
    #pragma unroll
    for (int k = 0; k < NS; k++) {
        float pk = __shfl_sync(FULL, R[k], k);
        float inv = __frcp_rn(pk);
        float f = R[k] * inv;
        if (lane == k) { myinv = inv; f = 0.0f; }
        #pragma unroll
        for (int j = k + 1; j < NS; j++) {
            float pj = __shfl_sync(FULL, R[j], k);
            R[j] = fmaf(-f, pj, R[j]);
        }
        float p1 = __shfl_sync(FULL, b1, k);
        float p2 = __shfl_sync(FULL, b2, k);
        b1 = fmaf(-f, p1, b1);
        b2 = fmaf(-f, p2, b2);
    }
    float h1 = b1 * myinv;
    float h2 = b2 * myinv;

    float ab = 0.f, ag = 0.f;
    #pragma unroll
    for (int c = 0; c < NS; c++) {
        float hc = __shfl_sync(FULL, h1, c);
        float gc = __shfl_sync(FULL, h2, c);
        if (c <= lane) {
            float w = (float)(lane - c) + 0.5f;
            ab = fmaf(w, hc, ab);
            ag = fmaf(w, gc, ag);
        }
    }
    if (lane < NS) {
        const float f = 2.0f * DT * DT * DT;
        d_coef[NH + lane]      = -f * ab;                              // beta  [25,45)
        d_coef[NH + NS + lane] = fmaf((float)(lane + 1), DT, -f * ag); // gamma [45,65)
    }
    if (lane >= 29) d_coef[65 + (lane - 29)] = 0.0f;   // pad [65,68) only
}

// ---------------------------------------------------------------------------
// Fused kernel (R10 shape: 8 warps, 32 rows/warp, 1 thread/row).
// New epilogue: y/p/v parked in 3 smem floats per row (the dead x region),
// then outputs are generated directly into coalesced STG.128 — no wide
// smem round-trip. f4 index i covers row i/5, steps 4*(i%5)..+3 (20%4==0
// means a float4 never spans two rows).
// ---------------------------------------------------------------------------
__global__ void __launch_bounds__(ROWS) mpc_fused(
    const float* __restrict__ x, const float* __restrict__ gp,
    const float* __restrict__ gv, const float* __restrict__ Af,
    const float* __restrict__ Lq, float* __restrict__ out, int nB)
{
    __shared__ float sx[ROWS * NH];   // 25.6 KB; per-warp region reused for y/p/v
    __shared__ float scoef[NCOEF];

    const int t = threadIdx.x;
    const int warp = t >> 5;
    const int lane = t & 31;

    if (blockIdx.x == 0) {
        if (warp == 0) {
            solve_coeffs(Af, Lq, lane);
            __threadfence();
            __syncwarp();
            st_release(&d_flags[lane * 32], 1u);   // 32 replicas
        }
        return;
    }

    const int wbase = (blockIdx.x - 1) * ROWS + warp * 32;
    float* __restrict__ wreg = sx + warp * 32 * NH;   // warp-private 800 floats

    // 1) stage this warp's 32 rows (200 float4) via cp.async
    {
        const float4* __restrict__ xin = (const float4*)(x + (size_t)wbase * NH);
        const long long n4_total = (long long)nB * NH / 4;
        const long long i4base = (long long)wbase * NH / 4;
        #pragma unroll
        for (int i = lane; i < 32 * NH / 4; i += 32) {
            if (i4base + i < n4_total) {
                unsigned d = smem_u32(wreg + 4 * i);
                asm volatile("cp.async.cg.shared.global [%0], [%1], 16;\n"
                             :: "r"(d), "l"(xin + i));
            }
        }
        asm volatile("cp.async.commit_group;\n");
    }

    // 2) prefetch gp/gv while staging is in flight (coalesced 128B)
    const int b = wbase + lane;
    const bool live = (b < nB);
    const float p = live ? gp[b] : 0.f;
    const float v = live ? gv[b] : 0.f;

    // 3) coefficient readiness (hashed flag line; warp-uniform -> 1 request)
    {
        const unsigned* fp = &d_flags[(blockIdx.x & 31) * 32];
        if (ld_acquire(fp) == 0u) {
            while (ld_acquire(fp) == 0u) { __nanosleep(128); }
        }
    }

    // 4) coefficients -> smem (per-warp redundant copy; identical values)
    #pragma unroll
    for (int i = lane; i < NCOEF; i += 32) scoef[i] = d_coef[i];
    __syncwarp();

    // 5) wait staging
    asm volatile("cp.async.wait_group 0;\n");
    __syncwarp();

    const float* __restrict__ sq = scoef;
    const float* __restrict__ sb = scoef + NH;
    const float* __restrict__ sg = scoef + NH + NS;

    // y = x_row . q, two dependency chains
    const float* __restrict__ xr = wreg + lane * NH;   // stride 25: conflict-free
    float y0 = 0.f, y1 = 0.f;
    #pragma unroll
    for (int j = 0; j < 24; j += 2) {
        y0 = fmaf(xr[j],     sq[j],     y0);
        y1 = fmaf(xr[j + 1], sq[j + 1], y1);
    }
    const float y = fmaf(xr[24], sq[24], y0) + y1;

    __syncwarp();   // all x reads in this warp's region complete

    // 6) park y/p/v in the (now dead) warp region
    wreg[lane]      = y;
    wreg[32 + lane] = p;
    wreg[64 + lane] = v;
    __syncwarp();

    // 7) direct coalesced output: 160 float4 per warp (5 per lane)
    {
        float4* __restrict__ o4 = (float4*)(out + (size_t)wbase * NS);
        const long long o4_total = (long long)nB * NS / 4;
        const long long o4base = (long long)wbase * NS / 4;
        #pragma unroll
        for (int k = 0; k < 5; k++) {
            const int i = lane + 32 * k;       // f4 index within warp tile
            const int row = i / 5;
            const int s = 4 * (i % 5);
            const float yy = wreg[row];
            const float pp = wreg[32 + row];
            const float vv = wreg[64 + row];
            float4 r;
            r.x = fmaf(sb[s + 0], yy, fmaf(sg[s + 0], vv, pp));
            r.y = fmaf(sb[s + 1], yy, fmaf(sg[s + 1], vv, pp));
            r.z = fmaf(sb[s + 2], yy, fmaf(sg[s + 2], vv, pp));
            r.w = fmaf(sb[s + 3], yy, fmaf(sg[s + 3], vv, pp));
            if (o4base + i < o4_total) o4[i] = r;
        }
    }
}

extern "C" void kernel_launch(void* const* d_in, const int* in_sizes, int n_in,
                              void* d_out, int out_size) {
    const float* x  = (const float*)d_in[0];
    const float* gp = (const float*)d_in[1];
    const float* gv = (const float*)d_in[2];
    const float* Af = (const float*)d_in[3];
    const float* Lq = (const float*)d_in[4];
    float* out = (float*)d_out;

    const int nB = in_sizes[0] / NH;
    const int grid = (nB + ROWS - 1) / ROWS + 1;   // +1: coefficient block
    mpc_fused<<<grid, ROWS>>>(x, gp, gv, Af, Lq, out, nB);
}

// round 16
// speedup vs baseline: 1.9037x; 1.4815x over previous
#include <cuda_runtime.h>
#include <math.h>

#define NH 25
#define NS 20
#define DT (1.0f/60.0f)
#define EPS_ 1e-4f
#define PQ 5.0f
#define QV_ 200.0f
#define QA_ 1.0f

#define WARPS 8
#define TROWS (WARPS * 32)   // 256 rows per tile
#define NTILE 2              // tiles per block (double-buffered)
#define NCOEF 68             // q[25] | beta[20] | gamma[20] | pad[3]

__device__ float d_coef[NCOEF];
__device__ unsigned d_flags[32 * 32];   // replicated flag, one per 128B line

__device__ __forceinline__ unsigned smem_u32(const void* p) {
    return (unsigned)__cvta_generic_to_shared(p);
}
__device__ __forceinline__ unsigned ld_acquire(const unsigned* p) {
    unsigned v;
    asm volatile("ld.global.acquire.gpu.b32 %0, [%1];" : "=r"(v) : "l"(p));
    return v;
}
__device__ __forceinline__ void st_release(unsigned* p, unsigned v) {
    asm volatile("st.global.release.gpu.b32 [%0], %1;" :: "l"(p), "r"(v));
}

// ---------------------------------------------------------------------------
// Coefficient solve: one warp, registers + shuffles (verified rel_err 6.6e-7
// since R4). Runs once on block 0, overlapped with the grid's staging.
// ---------------------------------------------------------------------------
__device__ __noinline__ void solve_coeffs(const float* __restrict__ Af,
                                          const float* __restrict__ Lq, int lane) {
    const unsigned FULL = 0xffffffffu;
    const int lnh = (lane < NH) ? lane : 0;
    const float af = (lane < NH) ? Af[lane] : 0.0f;

    float tk = 0.0f;
    #pragma unroll
    for (int j = 0; j < NH; j++)
        tk = fmaf(Lq[j * NH + lnh], __shfl_sync(FULL, af, j), tk);

    float q = EPS_ * af;
    #pragma unroll
    for (int k = 0; k < NH; k++)
        q = fmaf(Lq[lnh * NH + k], __shfl_sync(FULL, tk, k), q);
    if (lane < NH) d_coef[lane] = q;

    float av = (lane < NH) ? q * af : 0.0f;
    #pragma unroll
    for (int o = 16; o; o >>= 1) av += __shfl_xor_sync(FULL, av, o);
    const float alpha = av;

    float M0 = 0.f, M1 = 0.f, M2 = 0.f;
    for (int r = lane; r < NS; r++) {
        float w = (r == NS - 1) ? PQ : 1.0f;
        float d = (float)(r - lane);
        M0 += w;
        M1 = fmaf(w, d, M1);
        M2 = fmaf(w, d * d, M2);
    }

    float R[NS];
    #pragma unroll
    for (int c2 = 0; c2 < NS; c2++) {
        int m = lane > c2 ? lane : c2;
        if (m >= NS) m = NS - 1;
        float m0 = __shfl_sync(FULL, M0, m);
        float m1 = __shfl_sync(FULL, M1, m);
        float m2 = __shfl_sync(FULL, M2, m);
        float dd = fabsf((float)(lane - c2));
        float v = 2.0f * DT * DT * fmaf(alpha, fmaf(dd, m1, m2), QV_ * m0);
        if (lane == c2) v += 2.0f * QA_ + EPS_;
        R[c2] = v;
    }
    float b1 = M1;
    float b2 = fmaf(alpha, fmaf((float)(lane + 1), M1, M2), QV_ * M0);

    float myinv = 1.0f;
    #pragma unroll
    for (int k = 0; k < NS; k++) {
        float pk = __shfl_sync(FULL, R[k], k);
        float inv = __frcp_rn(pk);
        float f = R[k] * inv;
        if (lane == k) { myinv = inv; f = 0.0f; }
        #pragma unroll
        for (int j = k + 1; j < NS; j++) {
            float pj = __shfl_sync(FULL, R[j], k);
            R[j] = fmaf(-f, pj, R[j]);
        }
        float p1 = __shfl_sync(FULL, b1, k);
        float p2 = __shfl_sync(FULL, b2, k);
        b1 = fmaf(-f, p1, b1);
        b2 = fmaf(-f, p2, b2);
    }
    float h1 = b1 * myinv;
    float h2 = b2 * myinv;

    float ab = 0.f, ag = 0.f;
    #pragma unroll
    for (int c = 0; c < NS; c++) {
        float hc = __shfl_sync(FULL, h1, c);
        float gc = __shfl_sync(FULL, h2, c);
        if (c <= lane) {
            float w = (float)(lane - c) + 0.5f;
            ab = fmaf(w, hc, ab);
            ag = fmaf(w, gc, ag);
        }
    }
    if (lane < NS) {
        const float f = 2.0f * DT * DT * DT;
        d_coef[NH + lane]      = -f * ab;                              // beta  [25,45)
        d_coef[NH + NS + lane] = fmaf((float)(lane + 1), DT, -f * ag); // gamma [45,65)
    }
    if (lane >= 29) d_coef[65 + (lane - 29)] = 0.0f;   // pad [65,68) only
}

// ---------------------------------------------------------------------------
// Fused kernel, double-buffered: each row-block handles 2 tiles of 256 rows.
// Both tiles' cp.async groups are issued up front (2x bytes in flight);
// tile0's compute+store overlaps tile1's loads (wait_group 1, then 0).
// Per-warp regions; warps fully independent. Epilogue = R10's proven staged
// coalesced store.
// ---------------------------------------------------------------------------
__global__ void __launch_bounds__(TROWS) mpc_fused(
    const float* __restrict__ x, const float* __restrict__ gp,
    const float* __restrict__ gv, const float* __restrict__ Af,
    const float* __restrict__ Lq, float* __restrict__ out, int nB)
{
    __shared__ float sx[NTILE][TROWS * NH];   // 2 x 25.6 KB
    __shared__ float scoef[NCOEF];

    const int t = threadIdx.x;
    const int warp = t >> 5;
    const int lane = t & 31;

    if (blockIdx.x == 0) {
        if (warp == 0) {
            solve_coeffs(Af, Lq, lane);
            __threadfence();
            __syncwarp();
            st_release(&d_flags[lane * 32], 1u);   // 32 replicas
        }
        return;
    }

    const int bid = blockIdx.x - 1;
    const long long n4_total = (long long)nB * NH / 4;

    int wbase[NTILE];
    // 1) issue BOTH tiles' staging (one commit group per tile)
    #pragma unroll
    for (int tt = 0; tt < NTILE; tt++) {
        wbase[tt] = (bid * NTILE + tt) * TROWS + warp * 32;
        const float4* __restrict__ xin = (const float4*)(x + (size_t)wbase[tt] * NH);
        float* wreg = sx[tt] + warp * 32 * NH;
        const long long i4base = (long long)wbase[tt] * NH / 4;
        #pragma unroll
        for (int i = lane; i < 32 * NH / 4; i += 32) {
            if (i4base + i < n4_total) {
                unsigned d = smem_u32(wreg + 4 * i);
                asm volatile("cp.async.cg.shared.global [%0], [%1], 16;\n"
                             :: "r"(d), "l"(xin + i));
            }
        }
        asm volatile("cp.async.commit_group;\n");
    }

    // 2) prefetch gp/gv for both tiles
    float pv[NTILE], vv[NTILE];
    bool live[NTILE];
    #pragma unroll
    for (int tt = 0; tt < NTILE; tt++) {
        const int b = wbase[tt] + lane;
        live[tt] = (b < nB);
        pv[tt] = live[tt] ? gp[b] : 0.f;
        vv[tt] = live[tt] ? gv[b] : 0.f;
    }

    // 3) coefficient readiness (hashed flag line; warp-uniform -> 1 request)
    {
        const unsigned* fp = &d_flags[(blockIdx.x & 31) * 32];
        if (ld_acquire(fp) == 0u) {
            while (ld_acquire(fp) == 0u) { __nanosleep(128); }
        }
    }

    // 4) coefficients -> smem (per-warp redundant copy; identical values)
    #pragma unroll
    for (int i = lane; i < NCOEF; i += 32) scoef[i] = d_coef[i];
    __syncwarp();

    const float* __restrict__ sq = scoef;
    const float* __restrict__ sb = scoef + NH;
    const float* __restrict__ sg = scoef + NH + NS;

    // 5) process tiles in order; tile0's compute/store overlaps tile1's loads
    #pragma unroll
    for (int tt = 0; tt < NTILE; tt++) {
        if (tt == 0) { asm volatile("cp.async.wait_group 1;\n"); }
        else         { asm volatile("cp.async.wait_group 0;\n"); }
        __syncwarp();

        float* __restrict__ wreg = sx[tt] + warp * 32 * NH;
        const float* __restrict__ xr = wreg + lane * NH;   // stride 25: conflict-free

        float y0 = 0.f, y1 = 0.f;
        #pragma unroll
        for (int j = 0; j < 24; j += 2) {
            y0 = fmaf(xr[j],     sq[j],     y0);
            y1 = fmaf(xr[j + 1], sq[j + 1], y1);
        }
        const float y = fmaf(xr[24], sq[24], y0) + y1;
        const float p = pv[tt];
        const float v = vv[tt];

        __syncwarp();   // own-region reads complete before overwrite

        // outputs packed at lane*20 in own region (80B rows, 16B aligned)
        float4* so4 = (float4*)(wreg + lane * NS);
        #pragma unroll
        for (int s4 = 0; s4 < NS / 4; s4++) {
            float4 r;
            r.x = fmaf(sb[4*s4 + 0], y, fmaf(sg[4*s4 + 0], v, p));
            r.y = fmaf(sb[4*s4 + 1], y, fmaf(sg[4*s4 + 1], v, p));
            r.z = fmaf(sb[4*s4 + 2], y, fmaf(sg[4*s4 + 2], v, p));
            r.w = fmaf(sb[4*s4 + 3], y, fmaf(sg[4*s4 + 3], v, p));
            so4[s4] = r;
        }
        __syncwarp();

        // coalesced copy out: 32 rows * 20 floats = 160 contiguous float4
        float4* __restrict__ o4 = (float4*)(out + (size_t)wbase[tt] * NS);
        const float4* so = (const float4*)wreg;
        const long long o4_total = (long long)nB * NS / 4;
        const long long o4base = (long long)wbase[tt] * NS / 4;
        #pragma unroll
        for (int i = lane; i < 32 * NS / 4; i += 32) {
            if (o4base + i < o4_total) o4[i] = so[i];
        }
        __syncwarp();   // stores drained from smem before (possible) reuse
    }
}

extern "C" void kernel_launch(void* const* d_in, const int* in_sizes, int n_in,
                              void* d_out, int out_size) {
    const float* x  = (const float*)d_in[0];
    const float* gp = (const float*)d_in[1];
    const float* gv = (const float*)d_in[2];
    const float* Af = (const float*)d_in[3];
    const float* Lq = (const float*)d_in[4];
    float* out = (float*)d_out;

    const int nB = in_sizes[0] / NH;
    const int rowsPerBlock = NTILE * TROWS;
    const int grid = (nB + rowsPerBlock - 1) / rowsPerBlock + 1;   // +1: solver block
    mpc_fused<<<grid, TROWS>>>(x, gp, gv, Af, Lq, out, nB);
}